// round 2
// baseline (speedup 1.0000x reference)
#include <cuda_runtime.h>

#define N_TOT 8192
#define DIMS  512
#define NI    8
#define NW    1024          // N_TOT / NI
#define MARGIN 0.3f
#define EPSF   1e-12f

// ---------------- scratch (static device globals; no allocation) ------------
__device__ float              g_sq[N_TOT];
__device__ float              g_protos[NW * DIMS];
__device__ float              g_psq[NW];
__device__ float              g_distap[N_TOT];
__device__ unsigned int       g_minneg[N_TOT];     // float-bits of min neg d2
__device__ unsigned long long g_protomin[N_TOT];   // (d2bits<<32)|class

// ---------------- init ------------------------------------------------------
__global__ void init_kernel() {
    int i = blockIdx.x * blockDim.x + threadIdx.x;
    if (i < N_TOT) {
        g_minneg[i]   = 0x7f800000u;                 // +inf
        g_protomin[i] = 0xFFFFFFFFFFFFFFFFull;
    }
}

// ---------------- per-class prep: sq norms, protos, psq, hardest positive ---
__global__ void prep_kernel(const float* __restrict__ x) {
    __shared__ float xs[NI][DIMS + 4];   // +4 pad: conflict-free row-strided reads
    __shared__ float dots[NI][NI];
    __shared__ float s_psq;
    const int cls = blockIdx.x;
    const int tid = threadIdx.x;         // 256 threads
    const float* base = x + (size_t)cls * NI * DIMS;

    for (int k = tid; k < NI * DIMS; k += 256)
        xs[k / DIMS][k % DIMS] = base[k];
    if (tid == 0) s_psq = 0.f;
    __syncthreads();

    // prototype + its squared norm
    float psq_part = 0.f;
    for (int d = tid; d < DIMS; d += 256) {
        float s = 0.f;
        #pragma unroll
        for (int r = 0; r < NI; r++) s += xs[r][d];
        s *= (1.0f / NI);
        g_protos[cls * DIMS + d] = s;
        psq_part += s * s;
    }
    atomicAdd(&s_psq, psq_part);

    // all 8x8 within-class dot products
    if (tid < NI * NI) {
        int a = tid >> 3, b = tid & 7;
        float dot = 0.f;
        for (int d = 0; d < DIMS; d++) dot = fmaf(xs[a][d], xs[b][d], dot);
        dots[a][b] = dot;
        if (a == b) g_sq[cls * NI + a] = dot;
    }
    __syncthreads();

    if (tid == 0) g_psq[cls] = s_psq;
    if (tid < NI) {
        int a = tid;
        float sqa = dots[a][a];
        float m = -1.f;
        #pragma unroll
        for (int b = 0; b < NI; b++) {
            float d2 = sqa + dots[b][b] - 2.f * dots[a][b];
            m = fmaxf(m, sqrtf(fmaxf(d2, EPSF)));
        }
        g_distap[cls * NI + a] = m;      // hardest positive distance
    }
}

// ---------------- fused GEMM + mining epilogue ------------------------------
// MODE 0: B = inputs  (8192 cols)  -> hardest-negative min d2 per row
// MODE 1: B = protos  (1024 cols)  -> argmin proto d2 per row (packed u64)
template <int MODE>
__global__ __launch_bounds__(256, 2)
void gemm_mine_kernel(const float* __restrict__ A, const float* __restrict__ B) {
    __shared__ float As[16][132];
    __shared__ float Bs[16][132];

    const int tid = threadIdx.x;
    const int tx  = tid & 15;        // col group
    const int ty  = tid >> 4;        // row group
    const int rowBase = blockIdx.y * 128;
    const int colBase = blockIdx.x * 128;

    float acc[8][8];
    #pragma unroll
    for (int i = 0; i < 8; i++)
        #pragma unroll
        for (int j = 0; j < 8; j++) acc[i][j] = 0.f;

    for (int k0 = 0; k0 < DIMS; k0 += 16) {
        // 128x16 tiles of A and B, float4 loads, stored transposed [k][m]
        #pragma unroll
        for (int l = 0; l < 2; l++) {
            int f4 = tid + l * 256;          // 0..511
            int m  = f4 >> 2;                // 0..127
            int kc = (f4 & 3) * 4;           // 0,4,8,12
            float4 va = *(const float4*)(A + (size_t)(rowBase + m) * DIMS + k0 + kc);
            As[kc + 0][m] = va.x; As[kc + 1][m] = va.y;
            As[kc + 2][m] = va.z; As[kc + 3][m] = va.w;
            float4 vb = *(const float4*)(B + (size_t)(colBase + m) * DIMS + k0 + kc);
            Bs[kc + 0][m] = vb.x; Bs[kc + 1][m] = vb.y;
            Bs[kc + 2][m] = vb.z; Bs[kc + 3][m] = vb.w;
        }
        __syncthreads();

        #pragma unroll
        for (int k = 0; k < 16; k++) {
            float a[8], b[8];
            #pragma unroll
            for (int i = 0; i < 8; i++) a[i] = As[k][ty + 16 * i];
            #pragma unroll
            for (int j = 0; j < 8; j++) b[j] = Bs[k][tx + 16 * j];
            #pragma unroll
            for (int i = 0; i < 8; i++)
                #pragma unroll
                for (int j = 0; j < 8; j++)
                    acc[i][j] = fmaf(a[i], b[j], acc[i][j]);
        }
        __syncthreads();
    }

    // -------- epilogue --------
    if (MODE == 0) {
        __shared__ unsigned s_min[128];
        for (int i = tid; i < 128; i += 256) s_min[i] = 0x7f800000u;
        __syncthreads();
        #pragma unroll
        for (int i = 0; i < 8; i++) {
            int r    = rowBase + ty + 16 * i;
            int rcls = r >> 3;
            float sqr = g_sq[r];
            float m = __int_as_float(0x7f800000);
            #pragma unroll
            for (int j = 0; j < 8; j++) {
                int c = colBase + tx + 16 * j;
                if ((c >> 3) != rcls) {
                    float d2 = fmaxf(sqr + g_sq[c] - 2.f * acc[i][j], 0.f);
                    m = fminf(m, d2);
                }
            }
            atomicMin(&s_min[ty + 16 * i], __float_as_uint(m));
        }
        __syncthreads();
        if (tid < 128) atomicMin(&g_minneg[rowBase + tid], s_min[tid]);
    } else {
        __shared__ unsigned long long s_key[128];
        for (int i = tid; i < 128; i += 256) s_key[i] = 0xFFFFFFFFFFFFFFFFull;
        __syncthreads();
        #pragma unroll
        for (int i = 0; i < 8; i++) {
            int r = rowBase + ty + 16 * i;
            float sqr = g_sq[r];
            unsigned long long kmin = 0xFFFFFFFFFFFFFFFFull;
            #pragma unroll
            for (int j = 0; j < 8; j++) {
                int c = colBase + tx + 16 * j;           // c IS the class id
                float d2 = fmaxf(sqr + g_psq[c] - 2.f * acc[i][j], 0.f);
                unsigned long long key =
                    ((unsigned long long)__float_as_uint(d2) << 32) | (unsigned)c;
                kmin = key < kmin ? key : kmin;
            }
            atomicMin(&s_key[ty + 16 * i], kmin);
        }
        __syncthreads();
        if (tid < 128) atomicMin(&g_protomin[rowBase + tid], s_key[tid]);
    }
}

// ---------------- finalize: reduce 4 scalars --------------------------------
__global__ void finalize_kernel(float* __restrict__ out) {
    __shared__ float red[4][8];
    const int tid = threadIdx.x;   // 256
    float ls = 0.f, dp = 0.f, dn = 0.f, ac = 0.f;
    for (int i = tid; i < N_TOT; i += 256) {
        float dap = g_distap[i];
        float dan = sqrtf(fmaxf(__uint_as_float(g_minneg[i]), EPSF));
        ls += fmaxf(dap - dan + MARGIN, 0.f);
        dp += dap;
        dn += dan;
        unsigned est = (unsigned)(g_protomin[i] & 0xffffffffull);
        ac += (est == (unsigned)(i >> 3)) ? 1.f : 0.f;
    }
    // warp reduce
    #pragma unroll
    for (int o = 16; o > 0; o >>= 1) {
        ls += __shfl_down_sync(0xffffffffu, ls, o);
        dp += __shfl_down_sync(0xffffffffu, dp, o);
        dn += __shfl_down_sync(0xffffffffu, dn, o);
        ac += __shfl_down_sync(0xffffffffu, ac, o);
    }
    int warp = tid >> 5, lane = tid & 31;
    if (lane == 0) { red[0][warp] = ls; red[1][warp] = dp; red[2][warp] = dn; red[3][warp] = ac; }
    __syncthreads();
    if (tid == 0) {
        float tls = 0, tdp = 0, tdn = 0, tac = 0;
        #pragma unroll
        for (int w = 0; w < 8; w++) { tls += red[0][w]; tdp += red[1][w]; tdn += red[2][w]; tac += red[3][w]; }
        const float inv = 1.0f / (float)N_TOT;
        out[0] = tls * inv;        // W * loss, W = 1
        out[1] = tac * inv;        // acc
        out[2] = tdp * inv;        // dist_p
        out[3] = tdn * inv;        // dist_n
    }
}

// ---------------- launch ----------------------------------------------------
extern "C" void kernel_launch(void* const* d_in, const int* in_sizes, int n_in,
                              void* d_out, int out_size) {
    // inputs: [0] float32 [8192,512], [1] int32 targets (implicit i/8) — pick by size
    const float* x = (const float*)d_in[0];
    if (n_in > 1 && in_sizes[0] != N_TOT * DIMS) x = (const float*)d_in[1];
    float* out = (float*)d_out;

    init_kernel<<<(N_TOT + 255) / 256, 256>>>();
    prep_kernel<<<NW, 256>>>(x);

    float* protos;
    cudaGetSymbolAddress((void**)&protos, g_protos);

    dim3 gridNeg(N_TOT / 128, N_TOT / 128);
    gemm_mine_kernel<0><<<gridNeg, 256>>>(x, x);

    dim3 gridPro(NW / 128, N_TOT / 128);
    gemm_mine_kernel<1><<<gridPro, 256>>>(x, protos);

    finalize_kernel<<<1, 256>>>(out);
}

// round 5
// speedup vs baseline: 3.1046x; 3.1046x over previous
#include <cuda_runtime.h>

#define N_TOT 8192
#define DIMS  512
#define NI    8
#define NW    1024          // N_TOT / NI
#define MARGIN 0.3f
#define EPSF   1e-12f

typedef unsigned long long u64;

// ---------------- scratch (static device globals; no allocation) ------------
__device__ float              g_sq[N_TOT];
__device__ float              g_protos[NW * DIMS];
__device__ float              g_psq[NW];
__device__ float              g_distap[N_TOT];
__device__ unsigned int       g_minneg[N_TOT];     // float-bits of min neg d2
__device__ unsigned long long g_protomin[N_TOT];   // (d2bits<<32)|class

// ---------------- f32x2 helpers ---------------------------------------------
__device__ __forceinline__ u64 pack2(float lo, float hi) {
    u64 r; asm("mov.b64 %0, {%1, %2};" : "=l"(r) : "f"(lo), "f"(hi)); return r;
}
__device__ __forceinline__ void unpack2(u64 v, float& lo, float& hi) {
    asm("mov.b64 {%0, %1}, %2;" : "=f"(lo), "=f"(hi) : "l"(v));
}
__device__ __forceinline__ void ffma2(u64& d, u64 a, u64 b) {
    asm("fma.rn.f32x2 %0, %1, %2, %0;" : "+l"(d) : "l"(a), "l"(b));
}

// ---------------- init ------------------------------------------------------
__global__ void init_kernel() {
    int i = blockIdx.x * blockDim.x + threadIdx.x;
    if (i < N_TOT) {
        g_minneg[i]   = 0x7f800000u;                 // +inf
        g_protomin[i] = 0xFFFFFFFFFFFFFFFFull;
    }
}

// ---------------- per-class prep: sq norms, protos, psq, hardest positive ---
__global__ void prep_kernel(const float* __restrict__ x) {
    __shared__ float xs[NI][DIMS + 4];
    __shared__ float dots[NI][NI];
    __shared__ float s_psq;
    const int cls = blockIdx.x;
    const int tid = threadIdx.x;         // 256 threads
    const float* base = x + (size_t)cls * NI * DIMS;

    for (int k = tid; k < NI * DIMS; k += 256)
        xs[k / DIMS][k % DIMS] = base[k];
    if (tid == 0) s_psq = 0.f;
    __syncthreads();

    float psq_part = 0.f;
    for (int d = tid; d < DIMS; d += 256) {
        float s = 0.f;
        #pragma unroll
        for (int r = 0; r < NI; r++) s += xs[r][d];
        s *= (1.0f / NI);
        g_protos[cls * DIMS + d] = s;
        psq_part += s * s;
    }
    atomicAdd(&s_psq, psq_part);

    if (tid < NI * NI) {
        int a = tid >> 3, b = tid & 7;
        float dot = 0.f;
        for (int d = 0; d < DIMS; d++) dot = fmaf(xs[a][d], xs[b][d], dot);
        dots[a][b] = dot;
        if (a == b) g_sq[cls * NI + a] = dot;
    }
    __syncthreads();

    if (tid == 0) g_psq[cls] = s_psq;
    if (tid < NI) {
        int a = tid;
        float sqa = dots[a][a];
        float m = -1.f;
        #pragma unroll
        for (int b = 0; b < NI; b++) {
            float d2 = sqa + dots[b][b] - 2.f * dots[a][b];
            m = fmaxf(m, sqrtf(fmaxf(d2, EPSF)));
        }
        g_distap[cls * NI + a] = m;
    }
}

// ---------------- fused GEMM + mining epilogue ------------------------------
// MODE 0: B = inputs, symmetric (only bx>=by blocks run; off-diag blocks mine
//         rows AND columns) -> hardest-negative min d2 per sample
// MODE 1: B = protos (1024 cols) -> argmin proto d2 per row (packed u64)
template <int MODE>
__global__ __launch_bounds__(256, 2)
void gemm_mine_kernel(const float* __restrict__ A, const float* __restrict__ B) {
    if (MODE == 0 && blockIdx.x < blockIdx.y) return;   // symmetry

    __shared__ float As[16][132];
    __shared__ float Bs[16][132];
    __shared__ float s_red[16][128];

    const int tid = threadIdx.x;
    const int tx  = tid & 15;        // col group: cols tx*8 .. tx*8+7
    const int ty  = tid >> 4;        // row group: rows ty*8 .. ty*8+7
    const int rowBase = blockIdx.y * 128;
    const int colBase = blockIdx.x * 128;

    u64 acc2[8][4];
    #pragma unroll
    for (int i = 0; i < 8; i++)
        #pragma unroll
        for (int j = 0; j < 4; j++) acc2[i][j] = 0ull;

    for (int k0 = 0; k0 < DIMS; k0 += 16) {
        #pragma unroll
        for (int l = 0; l < 2; l++) {
            int f4 = tid + l * 256;          // 0..511
            int m  = f4 >> 2;                // 0..127
            int kc = (f4 & 3) * 4;           // 0,4,8,12
            float4 va = *(const float4*)(A + (size_t)(rowBase + m) * DIMS + k0 + kc);
            As[kc + 0][m] = va.x; As[kc + 1][m] = va.y;
            As[kc + 2][m] = va.z; As[kc + 3][m] = va.w;
            float4 vb = *(const float4*)(B + (size_t)(colBase + m) * DIMS + k0 + kc);
            Bs[kc + 0][m] = vb.x; Bs[kc + 1][m] = vb.y;
            Bs[kc + 2][m] = vb.z; Bs[kc + 3][m] = vb.w;
        }
        __syncthreads();

        #pragma unroll
        for (int k = 0; k < 16; k++) {
            // A: two LDS.128, duplicated into f32x2 lanes
            float4 av0 = *(const float4*)&As[k][ty * 8];
            float4 av1 = *(const float4*)&As[k][ty * 8 + 4];
            u64 a2[8];
            a2[0] = pack2(av0.x, av0.x); a2[1] = pack2(av0.y, av0.y);
            a2[2] = pack2(av0.z, av0.z); a2[3] = pack2(av0.w, av0.w);
            a2[4] = pack2(av1.x, av1.x); a2[5] = pack2(av1.y, av1.y);
            a2[6] = pack2(av1.z, av1.z); a2[7] = pack2(av1.w, av1.w);
            // B: four LDS.64 (adjacent column pairs)
            u64 b2[4];
            b2[0] = *(const u64*)&Bs[k][tx * 8 + 0];
            b2[1] = *(const u64*)&Bs[k][tx * 8 + 2];
            b2[2] = *(const u64*)&Bs[k][tx * 8 + 4];
            b2[3] = *(const u64*)&Bs[k][tx * 8 + 6];
            #pragma unroll
            for (int i = 0; i < 8; i++)
                #pragma unroll
                for (int j = 0; j < 4; j++)
                    ffma2(acc2[i][j], a2[i], b2[j]);
        }
        __syncthreads();
    }

    // -------- epilogue --------
    const float INF = __int_as_float(0x7f800000);

    if (MODE == 0) {
        const bool diag = (rowBase == colBase);
        float sqr[8], sqc[8];
        #pragma unroll
        for (int i = 0; i < 8; i++) sqr[i] = g_sq[rowBase + ty * 8 + i];
        #pragma unroll
        for (int j = 0; j < 8; j++) sqc[j] = g_sq[colBase + tx * 8 + j];

        float rmin[8], cmin[8];
        #pragma unroll
        for (int i = 0; i < 8; i++) rmin[i] = INF;
        #pragma unroll
        for (int j = 0; j < 8; j++) cmin[j] = INF;

        #pragma unroll
        for (int i = 0; i < 8; i++) {
            int r = rowBase + ty * 8 + i;
            int rcls = r >> 3;
            #pragma unroll
            for (int jj = 0; jj < 4; jj++) {
                float dlo, dhi;
                unpack2(acc2[i][jj], dlo, dhi);
                int j0 = 2 * jj, j1 = 2 * jj + 1;
                float d2a = fmaxf(sqr[i] + sqc[j0] - 2.f * dlo, 0.f);
                float d2b = fmaxf(sqr[i] + sqc[j1] - 2.f * dhi, 0.f);
                if (diag) {
                    int c0 = colBase + tx * 8 + j0;
                    if ((c0 >> 3) == rcls) d2a = INF;
                    if (((c0 + 1) >> 3) == rcls) d2b = INF;
                }
                rmin[i] = fminf(rmin[i], fminf(d2a, d2b));
                cmin[j0] = fminf(cmin[j0], d2a);
                cmin[j1] = fminf(cmin[j1], d2b);
            }
        }

        // row reduction: s_red[tx][row]
        #pragma unroll
        for (int i = 0; i < 8; i++) s_red[tx][ty * 8 + i] = rmin[i];
        __syncthreads();
        if (tid < 128) {
            float m = INF;
            #pragma unroll
            for (int w = 0; w < 16; w++) m = fminf(m, s_red[w][tid]);
            atomicMin(&g_minneg[rowBase + tid], __float_as_uint(m));
        }
        __syncthreads();

        if (!diag) {
            // column reduction: s_red[ty][col]
            #pragma unroll
            for (int j = 0; j < 8; j++) s_red[ty][tx * 8 + j] = cmin[j];
            __syncthreads();
            if (tid < 128) {
                float m = INF;
                #pragma unroll
                for (int w = 0; w < 16; w++) m = fminf(m, s_red[w][tid]);
                atomicMin(&g_minneg[colBase + tid], __float_as_uint(m));
            }
        }
    } else {
        __shared__ unsigned long long s_key[128];
        for (int i = tid; i < 128; i += 256) s_key[i] = 0xFFFFFFFFFFFFFFFFull;
        __syncthreads();
        float sqc[8];
        #pragma unroll
        for (int j = 0; j < 8; j++) sqc[j] = g_psq[colBase + tx * 8 + j];
        #pragma unroll
        for (int i = 0; i < 8; i++) {
            int r = rowBase + ty * 8 + i;
            float sqr = g_sq[r];
            unsigned long long kmin = 0xFFFFFFFFFFFFFFFFull;
            #pragma unroll
            for (int jj = 0; jj < 4; jj++) {
                float dlo, dhi;
                unpack2(acc2[i][jj], dlo, dhi);
                int c0 = colBase + tx * 8 + 2 * jj;
                float d2a = fmaxf(sqr + sqc[2 * jj]     - 2.f * dlo, 0.f);
                float d2b = fmaxf(sqr + sqc[2 * jj + 1] - 2.f * dhi, 0.f);
                unsigned long long ka =
                    ((unsigned long long)__float_as_uint(d2a) << 32) | (unsigned)c0;
                unsigned long long kb =
                    ((unsigned long long)__float_as_uint(d2b) << 32) | (unsigned)(c0 + 1);
                kmin = ka < kmin ? ka : kmin;
                kmin = kb < kmin ? kb : kmin;
            }
            atomicMin(&s_key[ty * 8 + i], kmin);
        }
        __syncthreads();
        if (tid < 128) atomicMin(&g_protomin[rowBase + tid], s_key[tid]);
    }
}

// ---------------- finalize: reduce 4 scalars --------------------------------
__global__ void finalize_kernel(float* __restrict__ out) {
    __shared__ float red[4][8];
    const int tid = threadIdx.x;   // 256
    float ls = 0.f, dp = 0.f, dn = 0.f, ac = 0.f;
    for (int i = tid; i < N_TOT; i += 256) {
        float dap = g_distap[i];
        float dan = sqrtf(fmaxf(__uint_as_float(g_minneg[i]), EPSF));
        ls += fmaxf(dap - dan + MARGIN, 0.f);
        dp += dap;
        dn += dan;
        unsigned est = (unsigned)(g_protomin[i] & 0xffffffffull);
        ac += (est == (unsigned)(i >> 3)) ? 1.f : 0.f;
    }
    #pragma unroll
    for (int o = 16; o > 0; o >>= 1) {
        ls += __shfl_down_sync(0xffffffffu, ls, o);
        dp += __shfl_down_sync(0xffffffffu, dp, o);
        dn += __shfl_down_sync(0xffffffffu, dn, o);
        ac += __shfl_down_sync(0xffffffffu, ac, o);
    }
    int warp = tid >> 5, lane = tid & 31;
    if (lane == 0) { red[0][warp] = ls; red[1][warp] = dp; red[2][warp] = dn; red[3][warp] = ac; }
    __syncthreads();
    if (tid == 0) {
        float tls = 0, tdp = 0, tdn = 0, tac = 0;
        #pragma unroll
        for (int w = 0; w < 8; w++) { tls += red[0][w]; tdp += red[1][w]; tdn += red[2][w]; tac += red[3][w]; }
        const float inv = 1.0f / (float)N_TOT;
        out[0] = tls * inv;
        out[1] = tac * inv;
        out[2] = tdp * inv;
        out[3] = tdn * inv;
    }
}

// ---------------- launch ----------------------------------------------------
extern "C" void kernel_launch(void* const* d_in, const int* in_sizes, int n_in,
                              void* d_out, int out_size) {
    const float* x = (const float*)d_in[0];
    if (n_in > 1 && in_sizes[0] != N_TOT * DIMS) x = (const float*)d_in[1];
    float* out = (float*)d_out;

    init_kernel<<<(N_TOT + 255) / 256, 256>>>();
    prep_kernel<<<NW, 256>>>(x);

    float* protos;
    cudaGetSymbolAddress((void**)&protos, g_protos);

    dim3 gridNeg(N_TOT / 128, N_TOT / 128);   // bx<by blocks early-exit
    gemm_mine_kernel<0><<<gridNeg, 256>>>(x, x);

    dim3 gridPro(NW / 128, N_TOT / 128);
    gemm_mine_kernel<1><<<gridPro, 256>>>(x, protos);

    finalize_kernel<<<1, 256>>>(out);
}

// round 9
// speedup vs baseline: 7.7059x; 2.4821x over previous
#include <cuda_runtime.h>
#include <cstdint>

#define N_TOT 8192
#define DIMS  512
#define NI    8
#define NW    1024          // N_TOT / NI
#define MARGIN 0.3f
#define EPSF   1e-12f

typedef unsigned int u32;
typedef unsigned long long u64;

// ---------------- scratch (static device globals; no allocation) ------------
__device__ float g_sq[N_TOT];
__device__ float g_protos[NW * DIMS];
__device__ float g_psq[NW];
__device__ float g_distap[N_TOT];
__device__ u32   g_minneg[N_TOT];     // float-bits of min neg d2
__device__ u64   g_protomin[N_TOT];   // (d2bits<<32)|class

// ---------------- init ------------------------------------------------------
__global__ void init_kernel() {
    int i = blockIdx.x * blockDim.x + threadIdx.x;
    if (i < N_TOT) {
        g_minneg[i]   = 0x7f800000u;
        g_protomin[i] = 0xFFFFFFFFFFFFFFFFull;
    }
}

// ---------------- per-class prep (fp32-exact) --------------------------------
__global__ void prep_kernel(const float* __restrict__ x) {
    __shared__ float xs[NI][DIMS + 4];
    __shared__ float dots[NI][NI];
    __shared__ float s_psq;
    const int cls = blockIdx.x;
    const int tid = threadIdx.x;
    const float* base = x + (size_t)cls * NI * DIMS;

    for (int k = tid; k < NI * DIMS; k += 256)
        xs[k / DIMS][k % DIMS] = base[k];
    if (tid == 0) s_psq = 0.f;
    __syncthreads();

    float psq_part = 0.f;
    for (int d = tid; d < DIMS; d += 256) {
        float s = 0.f;
        #pragma unroll
        for (int r = 0; r < NI; r++) s += xs[r][d];
        s *= (1.0f / NI);
        g_protos[cls * DIMS + d] = s;
        psq_part += s * s;
    }
    atomicAdd(&s_psq, psq_part);

    if (tid < NI * NI) {
        int a = tid >> 3, b = tid & 7;
        float dot = 0.f;
        for (int d = 0; d < DIMS; d++) dot = fmaf(xs[a][d], xs[b][d], dot);
        dots[a][b] = dot;
        if (a == b) g_sq[cls * NI + a] = dot;
    }
    __syncthreads();

    if (tid == 0) g_psq[cls] = s_psq;
    if (tid < NI) {
        int a = tid;
        float sqa = dots[a][a];
        float m = -1.f;
        #pragma unroll
        for (int b = 0; b < NI; b++) {
            float d2 = sqa + dots[b][b] - 2.f * dots[a][b];
            m = fmaxf(m, sqrtf(fmaxf(d2, EPSF)));
        }
        g_distap[cls * NI + a] = m;
    }
}

// ---------------- mma.sync tf32 helpers --------------------------------------
__device__ __forceinline__ void mma_tf32(float d[4], const u32 a[4], const u32 b[2]) {
    asm volatile(
        "mma.sync.aligned.m16n8k8.row.col.f32.tf32.tf32.f32 "
        "{%0,%1,%2,%3}, {%4,%5,%6,%7}, {%8,%9}, {%0,%1,%2,%3};"
        : "+f"(d[0]), "+f"(d[1]), "+f"(d[2]), "+f"(d[3])
        : "r"(a[0]), "r"(a[1]), "r"(a[2]), "r"(a[3]), "r"(b[0]), "r"(b[1]));
}
__device__ __forceinline__ void cpa16(u32 dst, const float* src) {
    asm volatile("cp.async.ca.shared.global [%0], [%1], 16;" :: "r"(dst), "l"(src));
}
__device__ __forceinline__ void cp_commit() {
    asm volatile("cp.async.commit_group;" ::: "memory");
}

// ---------------- fused tf32 mma GEMM + mining -------------------------------
// CTA tile 128x128, 8 warps (4 row x 2 col), warp tile 32x64 = 2x8 m16n8k8.
// K chunked by 16 floats, 2-stage cp.async double buffer.
// smem tile layout: [row][k] with row stride 20 floats (conflict-free frags).
// MODE 0: B = inputs, symmetric (bx>=by); mines row-min and (off-diag) col-min.
// MODE 1: B = protos; per-row argmin key.
#define TSTRIDE 20
#define TILE_F  (128 * TSTRIDE)          // floats per tile (2560)
#define STAGE_F (2 * TILE_F)             // A + B per stage (5120 floats)

template <int MODE>
__global__ __launch_bounds__(256)
void mma_gemm_kernel(const float* __restrict__ A, const float* __restrict__ B) {
    const int bx = blockIdx.x, by = blockIdx.y;
    if (MODE == 0 && bx < by) return;

    extern __shared__ float dsm[];       // 2 stages x 5120 floats = 40 KB
    __shared__ u32 s_rmin[128];
    __shared__ u32 s_cmin[128];
    __shared__ u64 s_key[128];
    __shared__ float s_sqc[128];

    const int tid  = threadIdx.x;        // 256
    const int wid  = tid >> 5;
    const int lane = tid & 31;
    const int g    = lane >> 2;          // 0..7
    const int tg   = lane & 3;           // 0..3
    const int rowBase = by * 128;
    const int colBase = bx * 128;
    const int rowOff  = (wid >> 1) * 32; // warp row band
    const int colOff  = (wid & 1) * 64;  // warp col band

    // --------- async tile loader (chunk = 16 k-floats) ----------
    auto load_stage = [&](int s, int c) {
        float* base = dsm + s * STAGE_F;
        const int k0 = c * 16;
        #pragma unroll
        for (int i = 0; i < 4; i++) {
            int f   = tid + i * 256;             // 0..1023
            int isB = f >> 9;                    // 0: A, 1: B
            int ff  = f & 511;
            int r   = ff >> 2;                   // 0..127
            int kc  = (ff & 3) * 4;              // 0,4,8,12
            const float* src = (isB ? B + (size_t)(colBase + r) * DIMS
                                    : A + (size_t)(rowBase + r) * DIMS) + k0 + kc;
            float* dstp = base + isB * TILE_F + r * TSTRIDE + kc;
            cpa16((u32)__cvta_generic_to_shared(dstp), src);
        }
        cp_commit();
    };

    float acc[2][8][4];
    #pragma unroll
    for (int mi = 0; mi < 2; mi++)
        #pragma unroll
        for (int nt = 0; nt < 8; nt++)
            #pragma unroll
            for (int q = 0; q < 4; q++) acc[mi][nt][q] = 0.f;

    load_stage(0, 0);
    load_stage(1, 1);

    for (int c = 0; c < 32; c++) {
        if (c < 31) asm volatile("cp.async.wait_group 1;" ::: "memory");
        else        asm volatile("cp.async.wait_group 0;" ::: "memory");
        __syncthreads();

        const float* Asb = dsm + (c & 1) * STAGE_F;
        const float* Bsb = Asb + TILE_F;
        #pragma unroll
        for (int h = 0; h < 2; h++) {
            const int kc = h * 8 + tg;
            u32 afr[2][4];
            #pragma unroll
            for (int mi = 0; mi < 2; mi++) {
                const float* ap = Asb + (rowOff + mi * 16 + g) * TSTRIDE;
                afr[mi][0] = __float_as_uint(ap[kc]);
                afr[mi][1] = __float_as_uint(ap[8 * TSTRIDE + kc]);
                afr[mi][2] = __float_as_uint(ap[kc + 4]);
                afr[mi][3] = __float_as_uint(ap[8 * TSTRIDE + kc + 4]);
            }
            u32 bfr[8][2];
            #pragma unroll
            for (int nt = 0; nt < 8; nt++) {
                const float* bp = Bsb + (colOff + nt * 8 + g) * TSTRIDE;
                bfr[nt][0] = __float_as_uint(bp[kc]);
                bfr[nt][1] = __float_as_uint(bp[kc + 4]);
            }
            #pragma unroll
            for (int mi = 0; mi < 2; mi++)
                #pragma unroll
                for (int nt = 0; nt < 8; nt++)
                    mma_tf32(acc[mi][nt], afr[mi], bfr[nt]);
        }
        __syncthreads();
        if (c + 2 < 32) load_stage(c & 1, c + 2);
    }

    // ---------------- epilogue: mine ----------------
    const float INF = __int_as_float(0x7f800000);
    if (tid < 128) {
        s_sqc[tid]  = (MODE == 0) ? g_sq[colBase + tid] : g_psq[colBase + tid];
        s_rmin[tid] = 0x7f800000u;
        s_cmin[tid] = 0x7f800000u;
        s_key[tid]  = 0xFFFFFFFFFFFFFFFFull;
    }
    __syncthreads();

    const bool diag = (MODE == 0) && (bx == by);

    if (MODE == 0) {
        float cm[8][2];
        #pragma unroll
        for (int nt = 0; nt < 8; nt++) { cm[nt][0] = INF; cm[nt][1] = INF; }

        #pragma unroll
        for (int mi = 0; mi < 2; mi++) {
            #pragma unroll
            for (int half = 0; half < 2; half++) {       // row r and r+8
                const int r = rowOff + mi * 16 + g + half * 8;   // 0..127
                const float sqr = g_sq[rowBase + r];
                float rmin = INF;
                #pragma unroll
                for (int nt = 0; nt < 8; nt++) {
                    #pragma unroll
                    for (int cc = 0; cc < 2; cc++) {
                        const int col = colOff + nt * 8 + 2 * tg + cc;
                        float dot = acc[mi][nt][half * 2 + cc];
                        float d2 = fmaxf(sqr + s_sqc[col] - 2.f * dot, 0.f);
                        if (diag && ((r >> 3) == (col >> 3))) d2 = INF;
                        rmin = fminf(rmin, d2);
                        cm[nt][cc] = fminf(cm[nt][cc], d2);
                    }
                }
                atomicMin(&s_rmin[r], __float_as_uint(rmin));
            }
        }
        if (!diag) {
            // fold col-mins across the warp's 32 rows (lanes differing in g)
            #pragma unroll
            for (int off = 4; off < 32; off <<= 1)
                #pragma unroll
                for (int nt = 0; nt < 8; nt++) {
                    cm[nt][0] = fminf(cm[nt][0], __shfl_xor_sync(0xffffffffu, cm[nt][0], off));
                    cm[nt][1] = fminf(cm[nt][1], __shfl_xor_sync(0xffffffffu, cm[nt][1], off));
                }
            if (g == 0) {
                #pragma unroll
                for (int nt = 0; nt < 8; nt++) {
                    atomicMin(&s_cmin[colOff + nt * 8 + 2 * tg],     __float_as_uint(cm[nt][0]));
                    atomicMin(&s_cmin[colOff + nt * 8 + 2 * tg + 1], __float_as_uint(cm[nt][1]));
                }
            }
        }
        __syncthreads();
        if (tid < 128) {
            atomicMin(&g_minneg[rowBase + tid], s_rmin[tid]);
            if (!diag) atomicMin(&g_minneg[colBase + tid], s_cmin[tid]);
        }
    } else {
        #pragma unroll
        for (int mi = 0; mi < 2; mi++) {
            #pragma unroll
            for (int half = 0; half < 2; half++) {
                const int r = rowOff + mi * 16 + g + half * 8;
                const float sqr = g_sq[rowBase + r];
                u64 kmin = 0xFFFFFFFFFFFFFFFFull;
                #pragma unroll
                for (int nt = 0; nt < 8; nt++) {
                    #pragma unroll
                    for (int cc = 0; cc < 2; cc++) {
                        const int col = colOff + nt * 8 + 2 * tg + cc;
                        float dot = acc[mi][nt][half * 2 + cc];
                        float d2 = fmaxf(sqr + s_sqc[col] - 2.f * dot, 0.f);
                        u64 key = ((u64)__float_as_uint(d2) << 32) | (u32)(colBase + col);
                        kmin = key < kmin ? key : kmin;
                    }
                }
                // reduce across the 4 lanes sharing this row (xor 1, 2)
                #pragma unroll
                for (int off = 1; off < 4; off <<= 1) {
                    u64 o = __shfl_xor_sync(0xffffffffu, kmin, off);
                    kmin = o < kmin ? o : kmin;
                }
                if (tg == 0) atomicMin(&s_key[r], kmin);
            }
        }
        __syncthreads();
        if (tid < 128) atomicMin(&g_protomin[rowBase + tid], s_key[tid]);
    }
}

// ---------------- finalize: reduce 4 scalars --------------------------------
__global__ void finalize_kernel(float* __restrict__ out) {
    __shared__ float red[4][8];
    const int tid = threadIdx.x;   // 256
    float ls = 0.f, dp = 0.f, dn = 0.f, ac = 0.f;
    for (int i = tid; i < N_TOT; i += 256) {
        float dap = g_distap[i];
        float dan = sqrtf(fmaxf(__uint_as_float(g_minneg[i]), EPSF));
        ls += fmaxf(dap - dan + MARGIN, 0.f);
        dp += dap;
        dn += dan;
        unsigned est = (unsigned)(g_protomin[i] & 0xffffffffull);
        ac += (est == (unsigned)(i >> 3)) ? 1.f : 0.f;
    }
    #pragma unroll
    for (int o = 16; o > 0; o >>= 1) {
        ls += __shfl_down_sync(0xffffffffu, ls, o);
        dp += __shfl_down_sync(0xffffffffu, dp, o);
        dn += __shfl_down_sync(0xffffffffu, dn, o);
        ac += __shfl_down_sync(0xffffffffu, ac, o);
    }
    int warp = tid >> 5, lane = tid & 31;
    if (lane == 0) { red[0][warp] = ls; red[1][warp] = dp; red[2][warp] = dn; red[3][warp] = ac; }
    __syncthreads();
    if (tid == 0) {
        float tls = 0, tdp = 0, tdn = 0, tac = 0;
        #pragma unroll
        for (int w = 0; w < 8; w++) { tls += red[0][w]; tdp += red[1][w]; tdn += red[2][w]; tac += red[3][w]; }
        const float inv = 1.0f / (float)N_TOT;
        out[0] = tls * inv;
        out[1] = tac * inv;
        out[2] = tdp * inv;
        out[3] = tdn * inv;
    }
}

// ---------------- launch ----------------------------------------------------
#define DSMEM (2 * STAGE_F * 4)   // 40960 bytes (< 48KB, no attribute needed)

extern "C" void kernel_launch(void* const* d_in, const int* in_sizes, int n_in,
                              void* d_out, int out_size) {
    const float* x = (const float*)d_in[0];
    if (n_in > 1 && in_sizes[0] != N_TOT * DIMS) x = (const float*)d_in[1];
    float* out = (float*)d_out;

    init_kernel<<<(N_TOT + 255) / 256, 256>>>();
    prep_kernel<<<NW, 256>>>(x);

    float* protos;
    cudaGetSymbolAddress((void**)&protos, g_protos);

    dim3 gridNeg(N_TOT / 128, N_TOT / 128);   // 64 x 64, lower triangle exits
    mma_gemm_kernel<0><<<gridNeg, 256, DSMEM>>>(x, x);

    dim3 gridPro(NW / 128, N_TOT / 128);      // 8 x 64
    mma_gemm_kernel<1><<<gridPro, 256, DSMEM>>>(x, protos);

    finalize_kernel<<<1, 256>>>(out);
}

// round 10
// speedup vs baseline: 9.3912x; 1.2187x over previous
#include <cuda_runtime.h>
#include <cstdint>

#define N_TOT 8192
#define DIMS  512
#define NI    8
#define NW    1024          // N_TOT / NI
#define MARGIN 0.3f
#define EPSF   1e-12f

typedef unsigned int u32;
typedef unsigned long long u64;

// ---------------- scratch (static device globals; no allocation) ------------
__device__ float g_sq[N_TOT];
__device__ float g_protos[NW * DIMS];
__device__ float g_psq[NW];
__device__ float g_distap[N_TOT];
__device__ u32   g_minneg[N_TOT];     // float-bits of min neg d2
__device__ u64   g_protomin[N_TOT];   // (d2bits<<32)|class

// ---------------- per-class prep (fp32-exact) + init -------------------------
__global__ void prep_kernel(const float* __restrict__ x) {
    __shared__ float xs[NI][DIMS + 4];
    __shared__ float dots[NI][NI];
    __shared__ float s_psq;
    const int cls = blockIdx.x;
    const int tid = threadIdx.x;
    const float* base = x + (size_t)cls * NI * DIMS;

    if (tid < NI) {                       // fused init (1024 blocks x 8 = 8192)
        g_minneg[cls * NI + tid]   = 0x7f800000u;
        g_protomin[cls * NI + tid] = 0xFFFFFFFFFFFFFFFFull;
    }

    for (int k = tid; k < NI * DIMS; k += 256)
        xs[k / DIMS][k % DIMS] = base[k];
    if (tid == 0) s_psq = 0.f;
    __syncthreads();

    float psq_part = 0.f;
    for (int d = tid; d < DIMS; d += 256) {
        float s = 0.f;
        #pragma unroll
        for (int r = 0; r < NI; r++) s += xs[r][d];
        s *= (1.0f / NI);
        g_protos[cls * DIMS + d] = s;
        psq_part += s * s;
    }
    atomicAdd(&s_psq, psq_part);

    if (tid < NI * NI) {
        int a = tid >> 3, b = tid & 7;
        float dot = 0.f;
        for (int d = 0; d < DIMS; d++) dot = fmaf(xs[a][d], xs[b][d], dot);
        dots[a][b] = dot;
        if (a == b) g_sq[cls * NI + a] = dot;
    }
    __syncthreads();

    if (tid == 0) g_psq[cls] = s_psq;
    if (tid < NI) {
        int a = tid;
        float sqa = dots[a][a];
        float m = -1.f;
        #pragma unroll
        for (int b = 0; b < NI; b++) {
            float d2 = sqa + dots[b][b] - 2.f * dots[a][b];
            m = fmaxf(m, sqrtf(fmaxf(d2, EPSF)));
        }
        g_distap[cls * NI + a] = m;
    }
}

// ---------------- mma.sync tf32 helpers --------------------------------------
__device__ __forceinline__ void mma_tf32(float d[4], const u32 a[4], const u32 b[2]) {
    asm volatile(
        "mma.sync.aligned.m16n8k8.row.col.f32.tf32.tf32.f32 "
        "{%0,%1,%2,%3}, {%4,%5,%6,%7}, {%8,%9}, {%0,%1,%2,%3};"
        : "+f"(d[0]), "+f"(d[1]), "+f"(d[2]), "+f"(d[3])
        : "r"(a[0]), "r"(a[1]), "r"(a[2]), "r"(a[3]), "r"(b[0]), "r"(b[1]));
}
__device__ __forceinline__ void cpa16(u32 dst, const float* src) {
    asm volatile("cp.async.ca.shared.global [%0], [%1], 16;" :: "r"(dst), "l"(src));
}
__device__ __forceinline__ void cp_commit() {
    asm volatile("cp.async.commit_group;" ::: "memory");
}

// ---------------- fused tf32 mma GEMM + mining, merged grid ------------------
// Blocks [0, 2080): upper-triangle 64x64 self-Gram tiles (row+col mining).
// Blocks [2080, 2592): proto GEMM tiles (8 col-blocks x 64 row-blocks).
// CTA tile 128x128, 8 warps (4 row x 2 col), warp tile 32x64 = 2x8 m16n8k8.
// K chunked by 32 floats, 3-stage cp.async pipeline, 1 barrier per chunk.
// smem row stride 36 floats: fragment LDS bank = 4g+tg (permutation) -> CF.
#define TSTRIDE 36
#define TILE_F  (128 * TSTRIDE)          // 4608 floats per tile
#define STAGE_F (2 * TILE_F)             // 9216 floats per stage
#define NSTAGE  3
#define NCHUNK  16                       // 512 / 32
#define TRI_BLKS 2080                    // 64*65/2
#define DSMEM   (NSTAGE * STAGE_F * 4)   // 110592 bytes

__global__ __launch_bounds__(256, 2)
void mma_gemm_kernel(const float* __restrict__ A, const float* __restrict__ P) {
    extern __shared__ float dsm[];

    const int tid  = threadIdx.x;        // 256
    const int wid  = tid >> 5;
    const int lane = tid & 31;
    const int g    = lane >> 2;          // 0..7
    const int tg   = lane & 3;           // 0..3
    const int rowOff = (wid >> 1) * 32;
    const int colOff = (wid & 1) * 64;

    // ---- decode block -> (mode, rowBase, colBase) ----
    int mode, bxr, byr;
    if ((int)blockIdx.x < TRI_BLKS) {
        mode = 0;
        int t = blockIdx.x;
        int by = (int)(64.5f - sqrtf(64.5f * 64.5f - 2.0f * (float)t));
        // C(b) = b*(129-b)/2 blocks before row b; fix up float error
        while ((by + 1) * (129 - (by + 1)) / 2 <= t) ++by;
        while (by * (129 - by) / 2 > t) --by;
        byr = by;
        bxr = by + (t - by * (129 - by) / 2);
    } else {
        mode = 1;
        int p = blockIdx.x - TRI_BLKS;   // 0..511
        byr = p >> 3;
        bxr = p & 7;
    }
    const int rowBase = byr * 128;
    const int colBase = bxr * 128;
    const float* __restrict__ Bp = mode ? P : A;

    // ---- async stage loader (chunk = 32 k-floats) ----
    auto load_stage = [&](int slot, int c) {
        float* base = dsm + slot * STAGE_F;
        const int k0 = c * 32;
        #pragma unroll
        for (int i = 0; i < 8; i++) {
            int f   = tid + i * 256;             // 0..2047
            int isB = f >> 10;
            int ff  = f & 1023;
            int r   = ff >> 3;                   // 0..127
            int kc  = (ff & 7) * 4;              // 0..28
            const float* src = (isB ? Bp + (size_t)(colBase + r) * DIMS
                                    : A + (size_t)(rowBase + r) * DIMS) + k0 + kc;
            float* dstp = base + isB * TILE_F + r * TSTRIDE + kc;
            cpa16((u32)__cvta_generic_to_shared(dstp), src);
        }
    };

    float acc[2][8][4];
    #pragma unroll
    for (int mi = 0; mi < 2; mi++)
        #pragma unroll
        for (int nt = 0; nt < 8; nt++)
            #pragma unroll
            for (int q = 0; q < 4; q++) acc[mi][nt][q] = 0.f;

    load_stage(0, 0); cp_commit();
    load_stage(1, 1); cp_commit();

    for (int c = 0; c < NCHUNK; c++) {
        asm volatile("cp.async.wait_group 1;" ::: "memory");
        __syncthreads();
        if (c + 2 < NCHUNK) load_stage((c + 2) % NSTAGE, c + 2);
        cp_commit();                      // always commit (keeps group indexing)

        const float* Asb = dsm + (c % NSTAGE) * STAGE_F;
        const float* Bsb = Asb + TILE_F;
        #pragma unroll
        for (int h = 0; h < 4; h++) {
            const int kc = h * 8 + tg;
            u32 afr[2][4];
            #pragma unroll
            for (int mi = 0; mi < 2; mi++) {
                const float* ap = Asb + (rowOff + mi * 16 + g) * TSTRIDE;
                afr[mi][0] = __float_as_uint(ap[kc]);
                afr[mi][1] = __float_as_uint(ap[8 * TSTRIDE + kc]);
                afr[mi][2] = __float_as_uint(ap[kc + 4]);
                afr[mi][3] = __float_as_uint(ap[8 * TSTRIDE + kc + 4]);
            }
            u32 bfr[8][2];
            #pragma unroll
            for (int nt = 0; nt < 8; nt++) {
                const float* bp = Bsb + (colOff + nt * 8 + g) * TSTRIDE;
                bfr[nt][0] = __float_as_uint(bp[kc]);
                bfr[nt][1] = __float_as_uint(bp[kc + 4]);
            }
            #pragma unroll
            for (int mi = 0; mi < 2; mi++)
                #pragma unroll
                for (int nt = 0; nt < 8; nt++)
                    mma_tf32(acc[mi][nt], afr[mi], bfr[nt]);
        }
    }
    asm volatile("cp.async.wait_group 0;" ::: "memory");
    __syncthreads();                      // all LDS done -> safe to alias dsm

    // ---------------- epilogue: mine (arrays aliased into dsm) ----------------
    float* s_sqc  = dsm;                  // 128 f32
    u32*   s_rmin = (u32*)(dsm + 128);    // 128 u32
    u32*   s_cmin = (u32*)(dsm + 256);    // 128 u32
    u64*   s_key  = (u64*)(dsm + 384);    // 128 u64 (8B aligned)

    const float INF = __int_as_float(0x7f800000);
    if (tid < 128) {
        s_sqc[tid]  = (mode == 0) ? g_sq[colBase + tid] : g_psq[colBase + tid];
        s_rmin[tid] = 0x7f800000u;
        s_cmin[tid] = 0x7f800000u;
        s_key[tid]  = 0xFFFFFFFFFFFFFFFFull;
    }
    __syncthreads();

    const bool diag = (mode == 0) && (bxr == byr);

    if (mode == 0) {
        float cm[8][2];
        #pragma unroll
        for (int nt = 0; nt < 8; nt++) { cm[nt][0] = INF; cm[nt][1] = INF; }

        #pragma unroll
        for (int mi = 0; mi < 2; mi++) {
            #pragma unroll
            for (int half = 0; half < 2; half++) {
                const int r = rowOff + mi * 16 + g + half * 8;
                const float sqr = g_sq[rowBase + r];
                float rmin = INF;
                #pragma unroll
                for (int nt = 0; nt < 8; nt++) {
                    #pragma unroll
                    for (int cc = 0; cc < 2; cc++) {
                        const int col = colOff + nt * 8 + 2 * tg + cc;
                        float dot = acc[mi][nt][half * 2 + cc];
                        float d2 = fmaxf(sqr + s_sqc[col] - 2.f * dot, 0.f);
                        if (diag && ((r >> 3) == (col >> 3))) d2 = INF;
                        rmin = fminf(rmin, d2);
                        cm[nt][cc] = fminf(cm[nt][cc], d2);
                    }
                }
                atomicMin(&s_rmin[r], __float_as_uint(rmin));
            }
        }
        if (!diag) {
            #pragma unroll
            for (int off = 4; off < 32; off <<= 1)
                #pragma unroll
                for (int nt = 0; nt < 8; nt++) {
                    cm[nt][0] = fminf(cm[nt][0], __shfl_xor_sync(0xffffffffu, cm[nt][0], off));
                    cm[nt][1] = fminf(cm[nt][1], __shfl_xor_sync(0xffffffffu, cm[nt][1], off));
                }
            if (g == 0) {
                #pragma unroll
                for (int nt = 0; nt < 8; nt++) {
                    atomicMin(&s_cmin[colOff + nt * 8 + 2 * tg],     __float_as_uint(cm[nt][0]));
                    atomicMin(&s_cmin[colOff + nt * 8 + 2 * tg + 1], __float_as_uint(cm[nt][1]));
                }
            }
        }
        __syncthreads();
        if (tid < 128) {
            atomicMin(&g_minneg[rowBase + tid], s_rmin[tid]);
            if (!diag) atomicMin(&g_minneg[colBase + tid], s_cmin[tid]);
        }
    } else {
        #pragma unroll
        for (int mi = 0; mi < 2; mi++) {
            #pragma unroll
            for (int half = 0; half < 2; half++) {
                const int r = rowOff + mi * 16 + g + half * 8;
                const float sqr = g_sq[rowBase + r];
                u64 kmin = 0xFFFFFFFFFFFFFFFFull;
                #pragma unroll
                for (int nt = 0; nt < 8; nt++) {
                    #pragma unroll
                    for (int cc = 0; cc < 2; cc++) {
                        const int col = colOff + nt * 8 + 2 * tg + cc;
                        float dot = acc[mi][nt][half * 2 + cc];
                        float d2 = fmaxf(sqr + s_sqc[col] - 2.f * dot, 0.f);
                        u64 key = ((u64)__float_as_uint(d2) << 32) | (u32)(colBase + col);
                        kmin = key < kmin ? key : kmin;
                    }
                }
                #pragma unroll
                for (int off = 1; off < 4; off <<= 1) {
                    u64 o = __shfl_xor_sync(0xffffffffu, kmin, off);
                    kmin = o < kmin ? o : kmin;
                }
                if (tg == 0) atomicMin(&s_key[r], kmin);
            }
        }
        __syncthreads();
        if (tid < 128) atomicMin(&g_protomin[rowBase + tid], s_key[tid]);
    }
}

// ---------------- finalize: reduce 4 scalars --------------------------------
__global__ void finalize_kernel(float* __restrict__ out) {
    __shared__ float red[4][8];
    const int tid = threadIdx.x;   // 256
    float ls = 0.f, dp = 0.f, dn = 0.f, ac = 0.f;
    for (int i = tid; i < N_TOT; i += 256) {
        float dap = g_distap[i];
        float dan = sqrtf(fmaxf(__uint_as_float(g_minneg[i]), EPSF));
        ls += fmaxf(dap - dan + MARGIN, 0.f);
        dp += dap;
        dn += dan;
        unsigned est = (unsigned)(g_protomin[i] & 0xffffffffull);
        ac += (est == (unsigned)(i >> 3)) ? 1.f : 0.f;
    }
    #pragma unroll
    for (int o = 16; o > 0; o >>= 1) {
        ls += __shfl_down_sync(0xffffffffu, ls, o);
        dp += __shfl_down_sync(0xffffffffu, dp, o);
        dn += __shfl_down_sync(0xffffffffu, dn, o);
        ac += __shfl_down_sync(0xffffffffu, ac, o);
    }
    int warp = tid >> 5, lane = tid & 31;
    if (lane == 0) { red[0][warp] = ls; red[1][warp] = dp; red[2][warp] = dn; red[3][warp] = ac; }
    __syncthreads();
    if (tid == 0) {
        float tls = 0, tdp = 0, tdn = 0, tac = 0;
        #pragma unroll
        for (int w = 0; w < 8; w++) { tls += red[0][w]; tdp += red[1][w]; tdn += red[2][w]; tac += red[3][w]; }
        const float inv = 1.0f / (float)N_TOT;
        out[0] = tls * inv;
        out[1] = tac * inv;
        out[2] = tdp * inv;
        out[3] = tdn * inv;
    }
}

// ---------------- launch ----------------------------------------------------
extern "C" void kernel_launch(void* const* d_in, const int* in_sizes, int n_in,
                              void* d_out, int out_size) {
    const float* x = (const float*)d_in[0];
    if (n_in > 1 && in_sizes[0] != N_TOT * DIMS) x = (const float*)d_in[1];
    float* out = (float*)d_out;

    cudaFuncSetAttribute(mma_gemm_kernel,
                         cudaFuncAttributeMaxDynamicSharedMemorySize, DSMEM);

    prep_kernel<<<NW, 256>>>(x);

    float* protos;
    cudaGetSymbolAddress((void**)&protos, g_protos);

    mma_gemm_kernel<<<TRI_BLKS + 512, 256, DSMEM>>>(x, protos);

    finalize_kernel<<<1, 256>>>(out);
}